// round 11
// baseline (speedup 1.0000x reference)
#include <cuda_runtime.h>
#include <cuda_bf16.h>
#include <cuda_fp16.h>

#define BB 2
#define LL 64
#define DD 1024
#define HH 512
#define SSN 50000
#define VVN 40000
#define KK 32
#define MM 128
#define BKC 32
#define NTV 313     // ceil(40000/128)
#define NTY 391     // ceil(50000/128)

// ---------------- device scratch ----------------
__device__ float g_scale[LL];
__device__ float g_shift[LL];
__device__ __align__(16) __half g_hhi[MM * HH];           // h hi [m][k] fp16
__device__ __align__(16) __half g_hlo[MM * HH];           // h lo [m][k] fp16
__device__ __align__(16) __half g_vt[(size_t)VVN * MM];   // v^T fp16 [V][128]

// ---------------- smem layout (bytes) ----------------
#define A_HI_OFF 0          // [128][32] fp16, 64B rows, XOR swizzle (8192)
#define A_LO_OFF 8192
#define B_OFF    16384      // [32][136] fp16, 272B rows (8704)
#define STAGE_SZ 25088      // x2 stages = 50176
#define YS_PITCH 66         // ys[128][66] f32 = 33792 (overlays stage 0)
#define BIA_OFF  33792      // b_s[64]
#define SMEM_BYTES 50176

__device__ __forceinline__ unsigned smem_u32(const void* p) {
    unsigned a;
    asm("{ .reg .u64 t; cvta.to.shared.u64 t, %1; cvt.u32.u64 %0, t; }"
        : "=r"(a) : "l"(p));
    return a;
}
#define CP_ASYNC16(dst, src) \
    asm volatile("cp.async.cg.shared.global [%0], [%1], 16;" :: "r"(dst), "l"(src))
#define CP_COMMIT() asm volatile("cp.async.commit_group;" ::: "memory")
#define CP_WAIT0()  asm volatile("cp.async.wait_group 0;" ::: "memory")

__device__ __forceinline__ void ldsm4(unsigned& r0, unsigned& r1, unsigned& r2,
                                      unsigned& r3, unsigned addr) {
    asm volatile("ldmatrix.sync.aligned.m8n8.x4.shared.b16 {%0,%1,%2,%3}, [%4];"
                 : "=r"(r0), "=r"(r1), "=r"(r2), "=r"(r3) : "r"(addr));
}
__device__ __forceinline__ void ldsm4t(unsigned& r0, unsigned& r1, unsigned& r2,
                                       unsigned& r3, unsigned addr) {
    asm volatile("ldmatrix.sync.aligned.m8n8.x4.trans.shared.b16 {%0,%1,%2,%3}, [%4];"
                 : "=r"(r0), "=r"(r1), "=r"(r2), "=r"(r3) : "r"(addr));
}
__device__ __forceinline__ void mma_f16(float* d, const unsigned* a,
                                        unsigned b0, unsigned b1) {
    asm volatile(
        "mma.sync.aligned.m16n8k16.row.col.f32.f16.f16.f32 "
        "{%0,%1,%2,%3}, {%4,%5,%6,%7}, {%8,%9}, {%0,%1,%2,%3};"
        : "+f"(d[0]), "+f"(d[1]), "+f"(d[2]), "+f"(d[3])
        : "r"(a[0]), "r"(a[1]), "r"(a[2]), "r"(a[3]), "r"(b0), "r"(b1));
}

// ---------------------------------------------------------------------------
// Kernel 1: BN stats
// ---------------------------------------------------------------------------
__global__ void bn_stats_kernel(const float* __restrict__ x,
                                const float* __restrict__ gamma,
                                const float* __restrict__ beta) {
    int l = blockIdx.x, t = threadIdx.x;
    float s = 0.f, s2 = 0.f;
    for (int i = t; i < BB * DD; i += 256) {
        int b = i >> 10, d = i & (DD - 1);
        float v = x[(b * LL + l) * DD + d];
        s += v; s2 += v * v;
    }
    __shared__ float rs[256], rs2[256];
    rs[t] = s; rs2[t] = s2;
    __syncthreads();
    for (int o = 128; o > 0; o >>= 1) {
        if (t < o) { rs[t] += rs[t + o]; rs2[t] += rs2[t + o]; }
        __syncthreads();
    }
    if (t == 0) {
        const float inv_n = 1.f / (BB * DD);
        float mean = rs[0] * inv_n;
        float var  = rs2[0] * inv_n - mean * mean;
        float sc = gamma[l] * rsqrtf(var + 1e-5f);
        g_scale[l] = sc;
        g_shift[l] = beta[l] - mean * sc;
    }
}

// ---------------------------------------------------------------------------
// Kernel 2: h = relu(xn@W1+b1) -> fp16 hi/lo [m][k]; 4 bl-rows per block
// ---------------------------------------------------------------------------
__global__ __launch_bounds__(512) void h_kernel(const float* __restrict__ x,
                                                const float* __restrict__ W1,
                                                const float* __restrict__ b1) {
    __shared__ float xs[4][DD];   // 16 KB
    int t = threadIdx.x;
    int bl0 = blockIdx.x * 4;
    for (int i = t; i < 4 * DD; i += 512) {
        int r = i >> 10, d = i & (DD - 1);
        int bl = bl0 + r, l = bl & (LL - 1);
        xs[r][d] = x[bl * DD + d] * g_scale[l] + g_shift[l];
    }
    __syncthreads();
    float acc[4] = {0.f, 0.f, 0.f, 0.f};
#pragma unroll 8
    for (int d = 0; d < DD; ++d) {
        float w = W1[d * HH + t];
#pragma unroll
        for (int r = 0; r < 4; ++r) acc[r] += xs[r][d] * w;
    }
    float bj = b1[t];
#pragma unroll
    for (int r = 0; r < 4; ++r) {
        float v = fmaxf(acc[r] + bj, 0.f);
        __half hi = __float2half_rn(v);
        g_hhi[(bl0 + r) * HH + t] = hi;
        g_hlo[(bl0 + r) * HH + t] = __float2half_rn(v - __half2float(hi));
    }
}

// ---------------------------------------------------------------------------
// HMMA GEMM: both matrices in one grid. v-tiles (bid<NTV) write g_vt fp16;
// y-tiles write out fp32 directly. fp16 2-pass split: (A_hi + A_lo) @ B_fp16.
// ---------------------------------------------------------------------------
__global__ __launch_bounds__(256, 2) void gemm_kernel(const float* __restrict__ Wv,
                                                      const float* __restrict__ bv,
                                                      const float* __restrict__ Wy,
                                                      const float* __restrict__ by,
                                                      float* __restrict__ out) {
    extern __shared__ __align__(128) char smem[];
    const int t = threadIdx.x;
    const int lane = t & 31, w = t >> 5;
    const int wm = (w >> 2) * 64, wn = (w & 3) * 32;
    const bool isY = blockIdx.x >= NTV;
    const float* __restrict__ W    = isY ? Wy : Wv;
    const float* __restrict__ bias = isY ? by : bv;
    const int NN  = isY ? SSN : VVN;
    const int n0g = (isY ? blockIdx.x - NTV : blockIdx.x) * 128;
    const unsigned sb = smem_u32(smem);

    const int bk = t >> 3;              // B row (k)
    const int bn = (t & 7) * 16;        // B col base

    float acc[4][4][4];
#pragma unroll
    for (int i = 0; i < 4; ++i)
#pragma unroll
        for (int j = 0; j < 4; ++j)
#pragma unroll
            for (int e = 0; e < 4; ++e) acc[i][j][e] = 0.f;

    uint2 pBc[4];

    auto copyA = [&](int c) {
        unsigned stg = sb + (unsigned)(c & 1) * STAGE_SZ;
        int k0 = c * BKC;
#pragma unroll
        for (int j = 0; j < 2; ++j) {
            int id = t + 256 * j;
            int m = id >> 2, ch = id & 3;
            unsigned off = (unsigned)(m * 64 + ((ch ^ ((m >> 1) & 3))) * 16);
            CP_ASYNC16(stg + A_HI_OFF + off, &g_hhi[m * HH + k0 + ch * 8]);
            CP_ASYNC16(stg + A_LO_OFF + off, &g_hlo[m * HH + k0 + ch * 8]);
        }
    };
    auto prefB = [&](int c) {
        int k0 = c * BKC;
        const float* wr = W + (size_t)(k0 + bk) * NN + n0g + bn;
#pragma unroll
        for (int j = 0; j < 4; ++j) {
            int gn = n0g + bn + j * 4;
            float4 v = (gn < NN) ? *(const float4*)(wr + j * 4)
                                 : make_float4(0.f, 0.f, 0.f, 0.f);
            __half2 h0 = __floats2half2_rn(v.x, v.y);
            __half2 h1 = __floats2half2_rn(v.z, v.w);
            pBc[j].x = *(unsigned*)&h0;
            pBc[j].y = *(unsigned*)&h1;
        }
    };
    auto stsB = [&](int c) {
        char* st = smem + (c & 1) * STAGE_SZ;
#pragma unroll
        for (int j = 0; j < 4; ++j)
            *(uint2*)(st + B_OFF + bk * 272 + (bn + j * 4) * 2) = pBc[j];
    };

    copyA(0); CP_COMMIT();
    prefB(0); stsB(0);
    CP_WAIT0();
    __syncthreads();

    const unsigned bBase = (unsigned)((lane & 15) * 272 +
                                      (wn + (lane >> 4) * 8) * 2);

    for (int c = 0; c < HH / BKC; ++c) {
        if (c < HH / BKC - 1) {
            prefB(c + 1);
            copyA(c + 1); CP_COMMIT();
        }
        const unsigned stgb = sb + (unsigned)(c & 1) * STAGE_SZ;
#pragma unroll
        for (int ks = 0; ks < 2; ++ks) {
            unsigned ah[4][4], al[4][4], bf[2][4];
#pragma unroll
            for (int mi = 0; mi < 4; ++mi) {
                int row = wm + mi * 16 + (lane & 15);
                int chunk = (ks * 2 + (lane >> 4)) ^ ((row >> 1) & 3);
                ldsm4(ah[mi][0], ah[mi][1], ah[mi][2], ah[mi][3],
                      stgb + A_HI_OFF + row * 64 + chunk * 16);
            }
#pragma unroll
            for (int g = 0; g < 2; ++g)
                ldsm4t(bf[g][0], bf[g][1], bf[g][2], bf[g][3],
                       stgb + B_OFF + bBase + ks * 4352 + g * 32);
#pragma unroll
            for (int mi = 0; mi < 4; ++mi)
#pragma unroll
                for (int nj = 0; nj < 4; ++nj)
                    mma_f16(acc[mi][nj], ah[mi],
                            bf[nj >> 1][(nj & 1) * 2],
                            bf[nj >> 1][(nj & 1) * 2 + 1]);
#pragma unroll
            for (int mi = 0; mi < 4; ++mi) {
                int row = wm + mi * 16 + (lane & 15);
                int chunk = (ks * 2 + (lane >> 4)) ^ ((row >> 1) & 3);
                ldsm4(al[mi][0], al[mi][1], al[mi][2], al[mi][3],
                      stgb + A_LO_OFF + row * 64 + chunk * 16);
            }
#pragma unroll
            for (int mi = 0; mi < 4; ++mi)
#pragma unroll
                for (int nj = 0; nj < 4; ++nj)
                    mma_f16(acc[mi][nj], al[mi],
                            bf[nj >> 1][(nj & 1) * 2],
                            bf[nj >> 1][(nj & 1) * 2 + 1]);
        }
        if (c < HH / BKC - 1) {
            stsB(c + 1);
            CP_WAIT0();
            __syncthreads();
        }
    }
    __syncthreads();

    if (isY) {
        // direct float2 stores: lane owns (row, 2 consecutive cols)
#pragma unroll
        for (int mi = 0; mi < 4; ++mi)
#pragma unroll
            for (int nj = 0; nj < 4; ++nj) {
                int r0 = wm + mi * 16 + (lane >> 2);
                int col = wn + nj * 8 + (lane & 3) * 2;
                int gn = n0g + col;
                float* d = acc[mi][nj];
                if (gn + 1 < SSN) {
                    float2 bb = *(const float2*)&bias[gn];
                    *(float2*)&out[(size_t)r0 * SSN + gn] =
                        make_float2(d[0] + bb.x, d[1] + bb.y);
                    *(float2*)&out[(size_t)(r0 + 8) * SSN + gn] =
                        make_float2(d[2] + bb.x, d[3] + bb.y);
                } else if (gn < SSN) {
                    float b0 = __ldg(&bias[gn]);
                    out[(size_t)r0 * SSN + gn]       = d[0] + b0;
                    out[(size_t)(r0 + 8) * SSN + gn] = d[2] + b0;
                }
            }
    } else {
        // transpose through smem -> g_vt fp16 [n][m]
        float* ys  = (float*)smem;
        float* b_s = (float*)(smem + BIA_OFF);
#pragma unroll 1
        for (int hf = 0; hf < 2; ++hf) {
            const int h0 = hf * 64;
            if (t < 64) {
                int gn = n0g + h0 + t;
                b_s[t] = (gn < VVN) ? bias[gn] : 0.f;
            }
            if (((w & 3) >> 1) == hf) {
                int wn2 = ((w & 3) & 1) * 32;
#pragma unroll
                for (int mi = 0; mi < 4; ++mi)
#pragma unroll
                    for (int nj = 0; nj < 4; ++nj) {
                        int row = wm + mi * 16 + (lane >> 2);
                        int col = wn2 + nj * 8 + (lane & 3) * 2;
                        float* d = acc[mi][nj];
                        ys[row * YS_PITCH + col]           = d[0];
                        ys[row * YS_PITCH + col + 1]       = d[1];
                        ys[(row + 8) * YS_PITCH + col]     = d[2];
                        ys[(row + 8) * YS_PITCH + col + 1] = d[3];
                    }
            }
            __syncthreads();
            for (int i = t; i < 64 * 64; i += 256) {
                int r2 = i & 63, col = i >> 6;
                int gn = n0g + h0 + col;
                if (gn < VVN) {
                    float bvv = b_s[col];
                    __half2 pv = __floats2half2_rn(
                        ys[(2 * r2) * YS_PITCH + col] + bvv,
                        ys[(2 * r2 + 1) * YS_PITCH + col] + bvv);
                    *(__half2*)&g_vt[(size_t)gn * MM + 2 * r2] = pv;
                }
            }
            __syncthreads();
        }
    }
}

// ---------------------------------------------------------------------------
// Gather kernel: out[m, s] += 0.1 * sum_k w[s,k] * vt[idx[s,k]][m]
// block = 32 s-cols; warp = 4 cols; lane covers 4 m rows (8B of fp16 vt row)
// half2 accumulation via HFMA2 (issue-bound -> ~half the instructions)
// ---------------------------------------------------------------------------
__global__ __launch_bounds__(256) void gather_kernel(const float* __restrict__ slw,
                                                     const int* __restrict__ slidx,
                                                     float* __restrict__ out) {
    __shared__ float    sacc[32][132];   // pitch 132 f32 = 528 B (16-B aligned)
    __shared__ int      idx_s[1024];
    __shared__ unsigned w2_s[1024];      // packed half2(wk, wk)
    const int t = threadIdx.x, lane = t & 31, w = t >> 5;
    const int s0 = blockIdx.x * 32;

    for (int i = t; i < 1024; i += 256) {
        int gs = s0 + (i >> 5);
        bool ok = (gs < SSN);
        idx_s[i] = ok ? slidx[(size_t)gs * KK + (i & 31)] : 0;
        float wk = ok ? slw[(size_t)gs * KK + (i & 31)] : 0.f;
        __half2 p = __half2half2(__float2half_rn(wk));
        w2_s[i] = *(unsigned*)&p;
    }
    __syncthreads();

    __half2 acc[4][2];
#pragma unroll
    for (int c = 0; c < 4; ++c) {
        acc[c][0] = __half2half2(__ushort_as_half(0));
        acc[c][1] = __half2half2(__ushort_as_half(0));
    }

    const __half* vbase = &g_vt[lane * 4];
#pragma unroll 8
    for (int k = 0; k < KK; ++k) {
#pragma unroll
        for (int cj = 0; cj < 4; ++cj) {
            int ci = (w * 4 + cj) * KK + k;
            int ip = idx_s[ci];
            unsigned wraw = w2_s[ci];
            __half2 wk2 = *(__half2*)&wraw;
            uint2 raw = *(const uint2*)(vbase + (size_t)ip * MM);
            acc[cj][0] = __hfma2(*(__half2*)&raw.x, wk2, acc[cj][0]);
            acc[cj][1] = __hfma2(*(__half2*)&raw.y, wk2, acc[cj][1]);
        }
    }
    const int mb = lane * 4;
#pragma unroll
    for (int cj = 0; cj < 4; ++cj) {
        float2 f0 = __half22float2(acc[cj][0]);
        float2 f1 = __half22float2(acc[cj][1]);
        *(float4*)&sacc[w * 4 + cj][mb] = make_float4(f0.x, f0.y, f1.x, f1.y);
    }
    __syncthreads();

    for (int i = t; i < 32 * MM; i += 256) {
        int m = i >> 5, col = i & 31;
        int gs = s0 + col;
        if (gs < SSN)
            out[(size_t)m * SSN + gs] += 0.1f * sacc[col][m];
    }
}

// ---------------------------------------------------------------------------
extern "C" void kernel_launch(void* const* d_in, const int* in_sizes, int n_in,
                              void* d_out, int out_size) {
    const float* x     = (const float*)d_in[0];
    const float* gamma = (const float*)d_in[1];
    const float* beta  = (const float*)d_in[2];
    const float* W1    = (const float*)d_in[3];
    const float* b1    = (const float*)d_in[4];
    const float* W2    = (const float*)d_in[5];
    const float* b2    = (const float*)d_in[6];
    const float* Wslm  = (const float*)d_in[7];
    const float* bslm  = (const float*)d_in[8];
    const float* slw   = (const float*)d_in[9];
    const int*   slidx = (const int*)d_in[10];
    float* out = (float*)d_out;

    cudaFuncSetAttribute(gemm_kernel,
                         cudaFuncAttributeMaxDynamicSharedMemorySize, SMEM_BYTES);

    bn_stats_kernel<<<LL, 256>>>(x, gamma, beta);
    h_kernel<<<MM / 4, 512>>>(x, W1, b1);
    gemm_kernel<<<NTV + NTY, 256, SMEM_BYTES>>>(Wslm, bslm, W2, b2, out);
    gather_kernel<<<(SSN + 31) / 32, 256>>>(slw, slidx, out);
}

// round 12
// speedup vs baseline: 1.1186x; 1.1186x over previous
#include <cuda_runtime.h>
#include <cuda_bf16.h>
#include <cuda_fp16.h>

#define BB 2
#define LL 64
#define DD 1024
#define HH 512
#define SSN 50000
#define VVN 40000
#define KK 32
#define MM 128
#define BKC 32
#define NTV 313     // ceil(40000/128)
#define NTY 391     // ceil(50000/128)

// ---------------- device scratch ----------------
__device__ float g_scale[LL];
__device__ float g_shift[LL];
__device__ __align__(16) __half g_hhi[MM * HH];           // h hi [m][k] fp16
__device__ __align__(16) __half g_hlo[MM * HH];           // h lo [m][k] fp16
__device__ __align__(16) __half g_vt[(size_t)VVN * MM];   // v^T fp16 [V][128]

// ---------------- smem layout (bytes) ----------------
#define A_HI_OFF 0          // [128][32] fp16, 64B rows, XOR swizzle (8192)
#define A_LO_OFF 8192
#define B_OFF    16384      // [32][136] fp16, 272B rows (8704)
#define STAGE_SZ 25088      // x2 stages = 50176
#define YS_PITCH 66         // ys[128][66] f32 = 33792 (overlays stage 0)
#define BIA_OFF  33792      // b_s[64]
#define SMEM_BYTES 50176

__device__ __forceinline__ unsigned smem_u32(const void* p) {
    unsigned a;
    asm("{ .reg .u64 t; cvta.to.shared.u64 t, %1; cvt.u32.u64 %0, t; }"
        : "=r"(a) : "l"(p));
    return a;
}
#define CP_ASYNC16(dst, src) \
    asm volatile("cp.async.cg.shared.global [%0], [%1], 16;" :: "r"(dst), "l"(src))
#define CP_COMMIT() asm volatile("cp.async.commit_group;" ::: "memory")
#define CP_WAIT0()  asm volatile("cp.async.wait_group 0;" ::: "memory")

__device__ __forceinline__ void ldsm4(unsigned& r0, unsigned& r1, unsigned& r2,
                                      unsigned& r3, unsigned addr) {
    asm volatile("ldmatrix.sync.aligned.m8n8.x4.shared.b16 {%0,%1,%2,%3}, [%4];"
                 : "=r"(r0), "=r"(r1), "=r"(r2), "=r"(r3) : "r"(addr));
}
__device__ __forceinline__ void ldsm4t(unsigned& r0, unsigned& r1, unsigned& r2,
                                       unsigned& r3, unsigned addr) {
    asm volatile("ldmatrix.sync.aligned.m8n8.x4.trans.shared.b16 {%0,%1,%2,%3}, [%4];"
                 : "=r"(r0), "=r"(r1), "=r"(r2), "=r"(r3) : "r"(addr));
}
__device__ __forceinline__ void mma_f16(float* d, const unsigned* a,
                                        unsigned b0, unsigned b1) {
    asm volatile(
        "mma.sync.aligned.m16n8k16.row.col.f32.f16.f16.f32 "
        "{%0,%1,%2,%3}, {%4,%5,%6,%7}, {%8,%9}, {%0,%1,%2,%3};"
        : "+f"(d[0]), "+f"(d[1]), "+f"(d[2]), "+f"(d[3])
        : "r"(a[0]), "r"(a[1]), "r"(a[2]), "r"(a[3]), "r"(b0), "r"(b1));
}

// ---------------------------------------------------------------------------
// Kernel 1: BN stats
// ---------------------------------------------------------------------------
__global__ void bn_stats_kernel(const float* __restrict__ x,
                                const float* __restrict__ gamma,
                                const float* __restrict__ beta) {
    int l = blockIdx.x, t = threadIdx.x;
    float s = 0.f, s2 = 0.f;
    for (int i = t; i < BB * DD; i += 256) {
        int b = i >> 10, d = i & (DD - 1);
        float v = x[(b * LL + l) * DD + d];
        s += v; s2 += v * v;
    }
    __shared__ float rs[256], rs2[256];
    rs[t] = s; rs2[t] = s2;
    __syncthreads();
    for (int o = 128; o > 0; o >>= 1) {
        if (t < o) { rs[t] += rs[t + o]; rs2[t] += rs2[t + o]; }
        __syncthreads();
    }
    if (t == 0) {
        const float inv_n = 1.f / (BB * DD);
        float mean = rs[0] * inv_n;
        float var  = rs2[0] * inv_n - mean * mean;
        float sc = gamma[l] * rsqrtf(var + 1e-5f);
        g_scale[l] = sc;
        g_shift[l] = beta[l] - mean * sc;
    }
}

// ---------------------------------------------------------------------------
// Kernel 2: h = relu(xn@W1+b1) -> fp16 hi/lo [m][k]; 4 bl-rows per block
// ---------------------------------------------------------------------------
__global__ __launch_bounds__(512) void h_kernel(const float* __restrict__ x,
                                                const float* __restrict__ W1,
                                                const float* __restrict__ b1) {
    __shared__ float xs[4][DD];   // 16 KB
    int t = threadIdx.x;
    int bl0 = blockIdx.x * 4;
    for (int i = t; i < 4 * DD; i += 512) {
        int r = i >> 10, d = i & (DD - 1);
        int bl = bl0 + r, l = bl & (LL - 1);
        xs[r][d] = x[bl * DD + d] * g_scale[l] + g_shift[l];
    }
    __syncthreads();
    float acc[4] = {0.f, 0.f, 0.f, 0.f};
#pragma unroll 16
    for (int d = 0; d < DD; ++d) {
        float w = W1[d * HH + t];
#pragma unroll
        for (int r = 0; r < 4; ++r) acc[r] += xs[r][d] * w;
    }
    float bj = b1[t];
#pragma unroll
    for (int r = 0; r < 4; ++r) {
        float v = fmaxf(acc[r] + bj, 0.f);
        __half hi = __float2half_rn(v);
        g_hhi[(bl0 + r) * HH + t] = hi;
        g_hlo[(bl0 + r) * HH + t] = __float2half_rn(v - __half2float(hi));
    }
}

// ---------------------------------------------------------------------------
// HMMA GEMM: both matrices in one grid. v-tiles (bid<NTV) write g_vt fp16;
// y-tiles write out fp32 directly. fp16 2-pass split: (A_hi + A_lo) @ B_fp16.
// ---------------------------------------------------------------------------
__global__ __launch_bounds__(256, 2) void gemm_kernel(const float* __restrict__ Wv,
                                                      const float* __restrict__ bv,
                                                      const float* __restrict__ Wy,
                                                      const float* __restrict__ by,
                                                      float* __restrict__ out) {
    extern __shared__ __align__(128) char smem[];
    const int t = threadIdx.x;
    const int lane = t & 31, w = t >> 5;
    const int wm = (w >> 2) * 64, wn = (w & 3) * 32;
    const bool isY = blockIdx.x >= NTV;
    const float* __restrict__ W    = isY ? Wy : Wv;
    const float* __restrict__ bias = isY ? by : bv;
    const int NN  = isY ? SSN : VVN;
    const int n0g = (isY ? blockIdx.x - NTV : blockIdx.x) * 128;
    const unsigned sb = smem_u32(smem);

    const int bk = t >> 3;              // B row (k)
    const int bn = (t & 7) * 16;        // B col base

    float acc[4][4][4];
#pragma unroll
    for (int i = 0; i < 4; ++i)
#pragma unroll
        for (int j = 0; j < 4; ++j)
#pragma unroll
            for (int e = 0; e < 4; ++e) acc[i][j][e] = 0.f;

    uint2 pBc[4];

    auto copyA = [&](int c) {
        unsigned stg = sb + (unsigned)(c & 1) * STAGE_SZ;
        int k0 = c * BKC;
#pragma unroll
        for (int j = 0; j < 2; ++j) {
            int id = t + 256 * j;
            int m = id >> 2, ch = id & 3;
            unsigned off = (unsigned)(m * 64 + ((ch ^ ((m >> 1) & 3))) * 16);
            CP_ASYNC16(stg + A_HI_OFF + off, &g_hhi[m * HH + k0 + ch * 8]);
            CP_ASYNC16(stg + A_LO_OFF + off, &g_hlo[m * HH + k0 + ch * 8]);
        }
    };
    auto prefB = [&](int c) {
        int k0 = c * BKC;
        const float* wr = W + (size_t)(k0 + bk) * NN + n0g + bn;
#pragma unroll
        for (int j = 0; j < 4; ++j) {
            int gn = n0g + bn + j * 4;
            float4 v = (gn < NN) ? *(const float4*)(wr + j * 4)
                                 : make_float4(0.f, 0.f, 0.f, 0.f);
            __half2 h0 = __floats2half2_rn(v.x, v.y);
            __half2 h1 = __floats2half2_rn(v.z, v.w);
            pBc[j].x = *(unsigned*)&h0;
            pBc[j].y = *(unsigned*)&h1;
        }
    };
    auto stsB = [&](int c) {
        char* st = smem + (c & 1) * STAGE_SZ;
#pragma unroll
        for (int j = 0; j < 4; ++j)
            *(uint2*)(st + B_OFF + bk * 272 + (bn + j * 4) * 2) = pBc[j];
    };

    copyA(0); CP_COMMIT();
    prefB(0); stsB(0);
    CP_WAIT0();
    __syncthreads();

    const unsigned bBase = (unsigned)((lane & 15) * 272 +
                                      (wn + (lane >> 4) * 8) * 2);

    for (int c = 0; c < HH / BKC; ++c) {
        if (c < HH / BKC - 1) {
            prefB(c + 1);
            copyA(c + 1); CP_COMMIT();
        }
        const unsigned stgb = sb + (unsigned)(c & 1) * STAGE_SZ;
#pragma unroll
        for (int ks = 0; ks < 2; ++ks) {
            unsigned ah[4][4], al[4][4], bf[2][4];
#pragma unroll
            for (int mi = 0; mi < 4; ++mi) {
                int row = wm + mi * 16 + (lane & 15);
                int chunk = (ks * 2 + (lane >> 4)) ^ ((row >> 1) & 3);
                ldsm4(ah[mi][0], ah[mi][1], ah[mi][2], ah[mi][3],
                      stgb + A_HI_OFF + row * 64 + chunk * 16);
            }
#pragma unroll
            for (int g = 0; g < 2; ++g)
                ldsm4t(bf[g][0], bf[g][1], bf[g][2], bf[g][3],
                       stgb + B_OFF + bBase + ks * 4352 + g * 32);
#pragma unroll
            for (int mi = 0; mi < 4; ++mi)
#pragma unroll
                for (int nj = 0; nj < 4; ++nj)
                    mma_f16(acc[mi][nj], ah[mi],
                            bf[nj >> 1][(nj & 1) * 2],
                            bf[nj >> 1][(nj & 1) * 2 + 1]);
#pragma unroll
            for (int mi = 0; mi < 4; ++mi) {
                int row = wm + mi * 16 + (lane & 15);
                int chunk = (ks * 2 + (lane >> 4)) ^ ((row >> 1) & 3);
                ldsm4(al[mi][0], al[mi][1], al[mi][2], al[mi][3],
                      stgb + A_LO_OFF + row * 64 + chunk * 16);
            }
#pragma unroll
            for (int mi = 0; mi < 4; ++mi)
#pragma unroll
                for (int nj = 0; nj < 4; ++nj)
                    mma_f16(acc[mi][nj], al[mi],
                            bf[nj >> 1][(nj & 1) * 2],
                            bf[nj >> 1][(nj & 1) * 2 + 1]);
        }
        if (c < HH / BKC - 1) {
            stsB(c + 1);
            CP_WAIT0();
            __syncthreads();
        }
    }
    __syncthreads();

    if (isY) {
        // direct float2 stores: lane owns (row, 2 consecutive cols)
#pragma unroll
        for (int mi = 0; mi < 4; ++mi)
#pragma unroll
            for (int nj = 0; nj < 4; ++nj) {
                int r0 = wm + mi * 16 + (lane >> 2);
                int col = wn + nj * 8 + (lane & 3) * 2;
                int gn = n0g + col;
                float* d = acc[mi][nj];
                if (gn + 1 < SSN) {
                    float2 bb = *(const float2*)&bias[gn];
                    *(float2*)&out[(size_t)r0 * SSN + gn] =
                        make_float2(d[0] + bb.x, d[1] + bb.y);
                    *(float2*)&out[(size_t)(r0 + 8) * SSN + gn] =
                        make_float2(d[2] + bb.x, d[3] + bb.y);
                } else if (gn < SSN) {
                    float b0 = __ldg(&bias[gn]);
                    out[(size_t)r0 * SSN + gn]       = d[0] + b0;
                    out[(size_t)(r0 + 8) * SSN + gn] = d[2] + b0;
                }
            }
    } else {
        // transpose through smem -> g_vt fp16 [n][m]
        float* ys  = (float*)smem;
        float* b_s = (float*)(smem + BIA_OFF);
#pragma unroll 1
        for (int hf = 0; hf < 2; ++hf) {
            const int h0 = hf * 64;
            if (t < 64) {
                int gn = n0g + h0 + t;
                b_s[t] = (gn < VVN) ? bias[gn] : 0.f;
            }
            if (((w & 3) >> 1) == hf) {
                int wn2 = ((w & 3) & 1) * 32;
#pragma unroll
                for (int mi = 0; mi < 4; ++mi)
#pragma unroll
                    for (int nj = 0; nj < 4; ++nj) {
                        int row = wm + mi * 16 + (lane >> 2);
                        int col = wn2 + nj * 8 + (lane & 3) * 2;
                        float* d = acc[mi][nj];
                        ys[row * YS_PITCH + col]           = d[0];
                        ys[row * YS_PITCH + col + 1]       = d[1];
                        ys[(row + 8) * YS_PITCH + col]     = d[2];
                        ys[(row + 8) * YS_PITCH + col + 1] = d[3];
                    }
            }
            __syncthreads();
            for (int i = t; i < 64 * 64; i += 256) {
                int r2 = i & 63, col = i >> 6;
                int gn = n0g + h0 + col;
                if (gn < VVN) {
                    float bvv = b_s[col];
                    __half2 pv = __floats2half2_rn(
                        ys[(2 * r2) * YS_PITCH + col] + bvv,
                        ys[(2 * r2 + 1) * YS_PITCH + col] + bvv);
                    *(__half2*)&g_vt[(size_t)gn * MM + 2 * r2] = pv;
                }
            }
            __syncthreads();
        }
    }
}

// ---------------------------------------------------------------------------
// Gather kernel: out[m, s] += 0.1 * sum_k w[s,k] * vt[idx[s,k]][m]
// block = 32 s-cols; warp = 4 cols; lane covers 4 m rows (8B of fp16 vt row)
// k-loop software-pipelined: prefetch step k+1 while FMA-ing step k (MLP 8)
// ---------------------------------------------------------------------------
__global__ __launch_bounds__(256) void gather_kernel(const float* __restrict__ slw,
                                                     const int* __restrict__ slidx,
                                                     float* __restrict__ out) {
    __shared__ float    sacc[32][132];   // pitch 132 f32 = 528 B (16-B aligned)
    __shared__ int      idx_s[1024];
    __shared__ unsigned w2_s[1024];      // packed half2(wk, wk)
    const int t = threadIdx.x, lane = t & 31, w = t >> 5;
    const int s0 = blockIdx.x * 32;

    for (int i = t; i < 1024; i += 256) {
        int gs = s0 + (i >> 5);
        bool ok = (gs < SSN);
        idx_s[i] = ok ? slidx[(size_t)gs * KK + (i & 31)] : 0;
        float wk = ok ? slw[(size_t)gs * KK + (i & 31)] : 0.f;
        __half2 p = __half2half2(__float2half_rn(wk));
        w2_s[i] = *(unsigned*)&p;
    }
    __syncthreads();

    __half2 acc[4][2];
#pragma unroll
    for (int c = 0; c < 4; ++c) {
        acc[c][0] = __half2half2(__ushort_as_half(0));
        acc[c][1] = __half2half2(__ushort_as_half(0));
    }

    const __half* vbase = &g_vt[lane * 4];
    const int ciB = w * 4 * KK;

    uint2 cur[4], nxt[4];
#pragma unroll
    for (int cj = 0; cj < 4; ++cj)
        cur[cj] = *(const uint2*)(vbase + (size_t)idx_s[ciB + cj * KK] * MM);

#pragma unroll 4
    for (int k = 0; k < KK; ++k) {
        if (k + 1 < KK) {
#pragma unroll
            for (int cj = 0; cj < 4; ++cj)
                nxt[cj] = *(const uint2*)(vbase +
                          (size_t)idx_s[ciB + cj * KK + k + 1] * MM);
        }
#pragma unroll
        for (int cj = 0; cj < 4; ++cj) {
            unsigned wraw = w2_s[ciB + cj * KK + k];
            __half2 wk2 = *(__half2*)&wraw;
            acc[cj][0] = __hfma2(*(__half2*)&cur[cj].x, wk2, acc[cj][0]);
            acc[cj][1] = __hfma2(*(__half2*)&cur[cj].y, wk2, acc[cj][1]);
        }
#pragma unroll
        for (int cj = 0; cj < 4; ++cj) cur[cj] = nxt[cj];
    }

    const int mb = lane * 4;
#pragma unroll
    for (int cj = 0; cj < 4; ++cj) {
        float2 f0 = __half22float2(acc[cj][0]);
        float2 f1 = __half22float2(acc[cj][1]);
        *(float4*)&sacc[w * 4 + cj][mb] = make_float4(f0.x, f0.y, f1.x, f1.y);
    }
    __syncthreads();

    for (int i = t; i < 32 * MM; i += 256) {
        int m = i >> 5, col = i & 31;
        int gs = s0 + col;
        if (gs < SSN)
            out[(size_t)m * SSN + gs] += 0.1f * sacc[col][m];
    }
}

// ---------------------------------------------------------------------------
extern "C" void kernel_launch(void* const* d_in, const int* in_sizes, int n_in,
                              void* d_out, int out_size) {
    const float* x     = (const float*)d_in[0];
    const float* gamma = (const float*)d_in[1];
    const float* beta  = (const float*)d_in[2];
    const float* W1    = (const float*)d_in[3];
    const float* b1    = (const float*)d_in[4];
    const float* W2    = (const float*)d_in[5];
    const float* b2    = (const float*)d_in[6];
    const float* Wslm  = (const float*)d_in[7];
    const float* bslm  = (const float*)d_in[8];
    const float* slw   = (const float*)d_in[9];
    const int*   slidx = (const int*)d_in[10];
    float* out = (float*)d_out;

    cudaFuncSetAttribute(gemm_kernel,
                         cudaFuncAttributeMaxDynamicSharedMemorySize, SMEM_BYTES);

    bn_stats_kernel<<<LL, 256>>>(x, gamma, beta);
    h_kernel<<<MM / 4, 512>>>(x, W1, b1);
    gemm_kernel<<<NTV + NTY, 256, SMEM_BYTES>>>(Wslm, bslm, W2, b2, out);
    gather_kernel<<<(SSN + 31) / 32, 256>>>(slw, slidx, out);
}

// round 13
// speedup vs baseline: 1.2177x; 1.0886x over previous
#include <cuda_runtime.h>
#include <cuda_bf16.h>
#include <cuda_fp16.h>

#define BB 2
#define LL 64
#define DD 1024
#define HH 512
#define SSN 50000
#define VVN 40000
#define KK 32
#define MM 128
#define BKC 32
#define NTV 313     // ceil(40000/128)
#define NTY 391     // ceil(50000/128)

// ---------------- device scratch ----------------
__device__ float g_scale[LL];
__device__ float g_shift[LL];
__device__ __align__(16) __half g_h16[MM * HH];           // h fp16 [m][k]
__device__ __align__(16) __half g_vt[(size_t)VVN * MM];   // v^T fp16 [V][128]

// ---------------- smem layout (bytes) ----------------
#define A_OFF    0          // [128][32] fp16, 64B rows, XOR swizzle (8192)
#define B_OFF    8192       // [32][136] fp16, 272B rows (8704)
#define STAGE_SZ 16896      // x2 stages = 33792
#define YS_PITCH 66         // ys[128][66] f32 = 33792 (overlays stages)
#define BIA_OFF  33792      // b_s[64]
#define SMEM_BYTES 34048

__device__ __forceinline__ unsigned smem_u32(const void* p) {
    unsigned a;
    asm("{ .reg .u64 t; cvta.to.shared.u64 t, %1; cvt.u32.u64 %0, t; }"
        : "=r"(a) : "l"(p));
    return a;
}
#define CP_ASYNC16(dst, src) \
    asm volatile("cp.async.cg.shared.global [%0], [%1], 16;" :: "r"(dst), "l"(src))
#define CP_COMMIT() asm volatile("cp.async.commit_group;" ::: "memory")
#define CP_WAIT0()  asm volatile("cp.async.wait_group 0;" ::: "memory")

__device__ __forceinline__ void ldsm4(unsigned& r0, unsigned& r1, unsigned& r2,
                                      unsigned& r3, unsigned addr) {
    asm volatile("ldmatrix.sync.aligned.m8n8.x4.shared.b16 {%0,%1,%2,%3}, [%4];"
                 : "=r"(r0), "=r"(r1), "=r"(r2), "=r"(r3) : "r"(addr));
}
__device__ __forceinline__ void ldsm4t(unsigned& r0, unsigned& r1, unsigned& r2,
                                       unsigned& r3, unsigned addr) {
    asm volatile("ldmatrix.sync.aligned.m8n8.x4.trans.shared.b16 {%0,%1,%2,%3}, [%4];"
                 : "=r"(r0), "=r"(r1), "=r"(r2), "=r"(r3) : "r"(addr));
}
__device__ __forceinline__ void mma_f16(float* d, const unsigned* a,
                                        unsigned b0, unsigned b1) {
    asm volatile(
        "mma.sync.aligned.m16n8k16.row.col.f32.f16.f16.f32 "
        "{%0,%1,%2,%3}, {%4,%5,%6,%7}, {%8,%9}, {%0,%1,%2,%3};"
        : "+f"(d[0]), "+f"(d[1]), "+f"(d[2]), "+f"(d[3])
        : "r"(a[0]), "r"(a[1]), "r"(a[2]), "r"(a[3]), "r"(b0), "r"(b1));
}

// ---------------------------------------------------------------------------
// Kernel 1: BN stats
// ---------------------------------------------------------------------------
__global__ void bn_stats_kernel(const float* __restrict__ x,
                                const float* __restrict__ gamma,
                                const float* __restrict__ beta) {
    int l = blockIdx.x, t = threadIdx.x;
    float s = 0.f, s2 = 0.f;
    for (int i = t; i < BB * DD; i += 256) {
        int b = i >> 10, d = i & (DD - 1);
        float v = x[(b * LL + l) * DD + d];
        s += v; s2 += v * v;
    }
    __shared__ float rs[256], rs2[256];
    rs[t] = s; rs2[t] = s2;
    __syncthreads();
    for (int o = 128; o > 0; o >>= 1) {
        if (t < o) { rs[t] += rs[t + o]; rs2[t] += rs2[t + o]; }
        __syncthreads();
    }
    if (t == 0) {
        const float inv_n = 1.f / (BB * DD);
        float mean = rs[0] * inv_n;
        float var  = rs2[0] * inv_n - mean * mean;
        float sc = gamma[l] * rsqrtf(var + 1e-5f);
        g_scale[l] = sc;
        g_shift[l] = beta[l] - mean * sc;
    }
}

// ---------------------------------------------------------------------------
// Kernel 2: h = relu(xn@W1+b1) -> fp16 [m][k]; 4 bl-rows per block
// ---------------------------------------------------------------------------
__global__ __launch_bounds__(512) void h_kernel(const float* __restrict__ x,
                                                const float* __restrict__ W1,
                                                const float* __restrict__ b1) {
    __shared__ float xs[4][DD];   // 16 KB
    int t = threadIdx.x;
    int bl0 = blockIdx.x * 4;
    for (int i = t; i < 4 * DD; i += 512) {
        int r = i >> 10, d = i & (DD - 1);
        int bl = bl0 + r, l = bl & (LL - 1);
        xs[r][d] = x[bl * DD + d] * g_scale[l] + g_shift[l];
    }
    __syncthreads();
    float acc[4] = {0.f, 0.f, 0.f, 0.f};
#pragma unroll 16
    for (int d = 0; d < DD; ++d) {
        float w = W1[d * HH + t];
#pragma unroll
        for (int r = 0; r < 4; ++r) acc[r] += xs[r][d] * w;
    }
    float bj = b1[t];
#pragma unroll
    for (int r = 0; r < 4; ++r)
        g_h16[(bl0 + r) * HH + t] = __float2half_rn(fmaxf(acc[r] + bj, 0.f));
}

// ---------------------------------------------------------------------------
// HMMA GEMM: both matrices in one grid. v-tiles (bid<NTV) write g_vt fp16;
// y-tiles write out fp32 directly. Single-pass fp16: A16 @ B16 -> f32.
// ---------------------------------------------------------------------------
__global__ __launch_bounds__(256, 2) void gemm_kernel(const float* __restrict__ Wv,
                                                      const float* __restrict__ bv,
                                                      const float* __restrict__ Wy,
                                                      const float* __restrict__ by,
                                                      float* __restrict__ out) {
    extern __shared__ __align__(128) char smem[];
    const int t = threadIdx.x;
    const int lane = t & 31, w = t >> 5;
    const int wm = (w >> 2) * 64, wn = (w & 3) * 32;
    const bool isY = blockIdx.x >= NTV;
    const float* __restrict__ W    = isY ? Wy : Wv;
    const float* __restrict__ bias = isY ? by : bv;
    const int NN  = isY ? SSN : VVN;
    const int n0g = (isY ? blockIdx.x - NTV : blockIdx.x) * 128;
    const unsigned sb = smem_u32(smem);

    const int bk = t >> 3;              // B row (k)
    const int bn = (t & 7) * 16;        // B col base

    float acc[4][4][4];
#pragma unroll
    for (int i = 0; i < 4; ++i)
#pragma unroll
        for (int j = 0; j < 4; ++j)
#pragma unroll
            for (int e = 0; e < 4; ++e) acc[i][j][e] = 0.f;

    uint2 pBc[4];

    auto copyA = [&](int c) {
        unsigned stg = sb + (unsigned)(c & 1) * STAGE_SZ;
        int k0 = c * BKC;
#pragma unroll
        for (int j = 0; j < 2; ++j) {
            int id = t + 256 * j;
            int m = id >> 2, ch = id & 3;
            unsigned off = (unsigned)(m * 64 + ((ch ^ ((m >> 1) & 3))) * 16);
            CP_ASYNC16(stg + A_OFF + off, &g_h16[m * HH + k0 + ch * 8]);
        }
    };
    auto prefB = [&](int c) {
        int k0 = c * BKC;
        const float* wr = W + (size_t)(k0 + bk) * NN + n0g + bn;
#pragma unroll
        for (int j = 0; j < 4; ++j) {
            int gn = n0g + bn + j * 4;
            float4 v = (gn < NN) ? *(const float4*)(wr + j * 4)
                                 : make_float4(0.f, 0.f, 0.f, 0.f);
            __half2 h0 = __floats2half2_rn(v.x, v.y);
            __half2 h1 = __floats2half2_rn(v.z, v.w);
            pBc[j].x = *(unsigned*)&h0;
            pBc[j].y = *(unsigned*)&h1;
        }
    };
    auto stsB = [&](int c) {
        char* st = smem + (c & 1) * STAGE_SZ;
#pragma unroll
        for (int j = 0; j < 4; ++j)
            *(uint2*)(st + B_OFF + bk * 272 + (bn + j * 4) * 2) = pBc[j];
    };

    copyA(0); CP_COMMIT();
    prefB(0); stsB(0);
    CP_WAIT0();
    __syncthreads();

    const unsigned bBase = (unsigned)((lane & 15) * 272 +
                                      (wn + (lane >> 4) * 8) * 2);

    for (int c = 0; c < HH / BKC; ++c) {
        if (c < HH / BKC - 1) {
            prefB(c + 1);
            copyA(c + 1); CP_COMMIT();
        }
        const unsigned stgb = sb + (unsigned)(c & 1) * STAGE_SZ;
#pragma unroll
        for (int ks = 0; ks < 2; ++ks) {
            unsigned ah[4][4], bf[2][4];
#pragma unroll
            for (int mi = 0; mi < 4; ++mi) {
                int row = wm + mi * 16 + (lane & 15);
                int chunk = (ks * 2 + (lane >> 4)) ^ ((row >> 1) & 3);
                ldsm4(ah[mi][0], ah[mi][1], ah[mi][2], ah[mi][3],
                      stgb + A_OFF + row * 64 + chunk * 16);
            }
#pragma unroll
            for (int g = 0; g < 2; ++g)
                ldsm4t(bf[g][0], bf[g][1], bf[g][2], bf[g][3],
                       stgb + B_OFF + bBase + ks * 4352 + g * 32);
#pragma unroll
            for (int mi = 0; mi < 4; ++mi)
#pragma unroll
                for (int nj = 0; nj < 4; ++nj)
                    mma_f16(acc[mi][nj], ah[mi],
                            bf[nj >> 1][(nj & 1) * 2],
                            bf[nj >> 1][(nj & 1) * 2 + 1]);
        }
        if (c < HH / BKC - 1) {
            stsB(c + 1);
            CP_WAIT0();
            __syncthreads();
        }
    }
    __syncthreads();

    if (isY) {
        // direct float2 stores: lane owns (row, 2 consecutive cols)
#pragma unroll
        for (int mi = 0; mi < 4; ++mi)
#pragma unroll
            for (int nj = 0; nj < 4; ++nj) {
                int r0 = wm + mi * 16 + (lane >> 2);
                int col = wn + nj * 8 + (lane & 3) * 2;
                int gn = n0g + col;
                float* d = acc[mi][nj];
                if (gn + 1 < SSN) {
                    float2 bb = *(const float2*)&bias[gn];
                    *(float2*)&out[(size_t)r0 * SSN + gn] =
                        make_float2(d[0] + bb.x, d[1] + bb.y);
                    *(float2*)&out[(size_t)(r0 + 8) * SSN + gn] =
                        make_float2(d[2] + bb.x, d[3] + bb.y);
                } else if (gn < SSN) {
                    float b0 = __ldg(&bias[gn]);
                    out[(size_t)r0 * SSN + gn]       = d[0] + b0;
                    out[(size_t)(r0 + 8) * SSN + gn] = d[2] + b0;
                }
            }
    } else {
        // transpose through smem -> g_vt fp16 [n][m]
        float* ys  = (float*)smem;
        float* b_s = (float*)(smem + BIA_OFF);
#pragma unroll 1
        for (int hf = 0; hf < 2; ++hf) {
            const int h0 = hf * 64;
            if (t < 64) {
                int gn = n0g + h0 + t;
                b_s[t] = (gn < VVN) ? bias[gn] : 0.f;
            }
            if (((w & 3) >> 1) == hf) {
                int wn2 = ((w & 3) & 1) * 32;
#pragma unroll
                for (int mi = 0; mi < 4; ++mi)
#pragma unroll
                    for (int nj = 0; nj < 4; ++nj) {
                        int row = wm + mi * 16 + (lane >> 2);
                        int col = wn2 + nj * 8 + (lane & 3) * 2;
                        float* d = acc[mi][nj];
                        ys[row * YS_PITCH + col]           = d[0];
                        ys[row * YS_PITCH + col + 1]       = d[1];
                        ys[(row + 8) * YS_PITCH + col]     = d[2];
                        ys[(row + 8) * YS_PITCH + col + 1] = d[3];
                    }
            }
            __syncthreads();
            for (int i = t; i < 64 * 64; i += 256) {
                int r2 = i & 63, col = i >> 6;
                int gn = n0g + h0 + col;
                if (gn < VVN) {
                    float bvv = b_s[col];
                    __half2 pv = __floats2half2_rn(
                        ys[(2 * r2) * YS_PITCH + col] + bvv,
                        ys[(2 * r2 + 1) * YS_PITCH + col] + bvv);
                    *(__half2*)&g_vt[(size_t)gn * MM + 2 * r2] = pv;
                }
            }
            __syncthreads();
        }
    }
}

// ---------------------------------------------------------------------------
// Gather kernel: out[m, s] += 0.1 * sum_k w[s,k] * vt[idx[s,k]][m]
// block = 32 s-cols; warp = 4 cols; lane covers 4 m rows (8B of fp16 vt row)
// k-loop software-pipelined: prefetch step k+1 while FMA-ing step k (MLP 8)
// ---------------------------------------------------------------------------
__global__ __launch_bounds__(256) void gather_kernel(const float* __restrict__ slw,
                                                     const int* __restrict__ slidx,
                                                     float* __restrict__ out) {
    __shared__ float    sacc[32][132];   // pitch 132 f32 = 528 B (16-B aligned)
    __shared__ int      idx_s[1024];
    __shared__ unsigned w2_s[1024];      // packed half2(wk, wk)
    const int t = threadIdx.x, lane = t & 31, w = t >> 5;
    const int s0 = blockIdx.x * 32;

    for (int i = t; i < 1024; i += 256) {
        int gs = s0 + (i >> 5);
        bool ok = (gs < SSN);
        idx_s[i] = ok ? slidx[(size_t)gs * KK + (i & 31)] : 0;
        float wk = ok ? slw[(size_t)gs * KK + (i & 31)] : 0.f;
        __half2 p = __half2half2(__float2half_rn(wk));
        w2_s[i] = *(unsigned*)&p;
    }
    __syncthreads();

    __half2 acc[4][2];
#pragma unroll
    for (int c = 0; c < 4; ++c) {
        acc[c][0] = __half2half2(__ushort_as_half(0));
        acc[c][1] = __half2half2(__ushort_as_half(0));
    }

    const __half* vbase = &g_vt[lane * 4];
    const int ciB = w * 4 * KK;

    uint2 cur[4], nxt[4];
#pragma unroll
    for (int cj = 0; cj < 4; ++cj)
        cur[cj] = *(const uint2*)(vbase + (size_t)idx_s[ciB + cj * KK] * MM);

#pragma unroll 4
    for (int k = 0; k < KK; ++k) {
        if (k + 1 < KK) {
#pragma unroll
            for (int cj = 0; cj < 4; ++cj)
                nxt[cj] = *(const uint2*)(vbase +
                          (size_t)idx_s[ciB + cj * KK + k + 1] * MM);
        }
#pragma unroll
        for (int cj = 0; cj < 4; ++cj) {
            unsigned wraw = w2_s[ciB + cj * KK + k];
            __half2 wk2 = *(__half2*)&wraw;
            acc[cj][0] = __hfma2(*(__half2*)&cur[cj].x, wk2, acc[cj][0]);
            acc[cj][1] = __hfma2(*(__half2*)&cur[cj].y, wk2, acc[cj][1]);
        }
#pragma unroll
        for (int cj = 0; cj < 4; ++cj) cur[cj] = nxt[cj];
    }

    const int mb = lane * 4;
#pragma unroll
    for (int cj = 0; cj < 4; ++cj) {
        float2 f0 = __half22float2(acc[cj][0]);
        float2 f1 = __half22float2(acc[cj][1]);
        *(float4*)&sacc[w * 4 + cj][mb] = make_float4(f0.x, f0.y, f1.x, f1.y);
    }
    __syncthreads();

    for (int i = t; i < 32 * MM; i += 256) {
        int m = i >> 5, col = i & 31;
        int gs = s0 + col;
        if (gs < SSN)
            out[(size_t)m * SSN + gs] += 0.1f * sacc[col][m];
    }
}

// ---------------------------------------------------------------------------
extern "C" void kernel_launch(void* const* d_in, const int* in_sizes, int n_in,
                              void* d_out, int out_size) {
    const float* x     = (const float*)d_in[0];
    const float* gamma = (const float*)d_in[1];
    const float* beta  = (const float*)d_in[2];
    const float* W1    = (const float*)d_in[3];
    const float* b1    = (const float*)d_in[4];
    const float* W2    = (const float*)d_in[5];
    const float* b2    = (const float*)d_in[6];
    const float* Wslm  = (const float*)d_in[7];
    const float* bslm  = (const float*)d_in[8];
    const float* slw   = (const float*)d_in[9];
    const int*   slidx = (const int*)d_in[10];
    float* out = (float*)d_out;

    cudaFuncSetAttribute(gemm_kernel,
                         cudaFuncAttributeMaxDynamicSharedMemorySize, SMEM_BYTES);

    bn_stats_kernel<<<LL, 256>>>(x, gamma, beta);
    h_kernel<<<MM / 4, 512>>>(x, W1, b1);
    gemm_kernel<<<NTV + NTY, 256, SMEM_BYTES>>>(Wslm, bslm, W2, b2, out);
    gather_kernel<<<(SSN + 31) / 32, 256>>>(slw, slidx, out);
}

// round 14
// speedup vs baseline: 1.3245x; 1.0877x over previous
#include <cuda_runtime.h>
#include <cuda_bf16.h>
#include <cuda_fp16.h>

#define BB 2
#define LL 64
#define DD 1024
#define HH 512
#define SSN 50000
#define VVN 40000
#define KK 32
#define MM 128
#define BKC 32
#define NTV 313     // ceil(40000/128)
#define NTY 391     // ceil(50000/128)

// ---------------- device scratch ----------------
__device__ float g_scale[LL];
__device__ float g_shift[LL];
__device__ __align__(16) __half g_h16[MM * HH];           // h fp16 [m][k]
__device__ __align__(16) __half g_vt[(size_t)VVN * MM];   // v^T fp16 [V][128]

// ---------------- smem layout (bytes) ----------------
#define A_OFF    0          // [128][32] fp16, 64B rows, XOR swizzle (8192)
#define B_OFF    8192       // [32][136] fp16, 272B rows (8704)
#define STAGE_SZ 16896      // x2 stages = 33792
#define YS_PITCH 66         // ys[128][66] f32 = 33792 (overlays stages)
#define BIA_OFF  33792      // b_s[64]
#define SMEM_BYTES 34048

__device__ __forceinline__ unsigned smem_u32(const void* p) {
    unsigned a;
    asm("{ .reg .u64 t; cvta.to.shared.u64 t, %1; cvt.u32.u64 %0, t; }"
        : "=r"(a) : "l"(p));
    return a;
}
#define CP_ASYNC16(dst, src) \
    asm volatile("cp.async.cg.shared.global [%0], [%1], 16;" :: "r"(dst), "l"(src))
#define CP_COMMIT() asm volatile("cp.async.commit_group;" ::: "memory")
#define CP_WAIT0()  asm volatile("cp.async.wait_group 0;" ::: "memory")

__device__ __forceinline__ void ldsm4(unsigned& r0, unsigned& r1, unsigned& r2,
                                      unsigned& r3, unsigned addr) {
    asm volatile("ldmatrix.sync.aligned.m8n8.x4.shared.b16 {%0,%1,%2,%3}, [%4];"
                 : "=r"(r0), "=r"(r1), "=r"(r2), "=r"(r3) : "r"(addr));
}
__device__ __forceinline__ void ldsm4t(unsigned& r0, unsigned& r1, unsigned& r2,
                                       unsigned& r3, unsigned addr) {
    asm volatile("ldmatrix.sync.aligned.m8n8.x4.trans.shared.b16 {%0,%1,%2,%3}, [%4];"
                 : "=r"(r0), "=r"(r1), "=r"(r2), "=r"(r3) : "r"(addr));
}
__device__ __forceinline__ void mma_f16(float* d, const unsigned* a,
                                        unsigned b0, unsigned b1) {
    asm volatile(
        "mma.sync.aligned.m16n8k16.row.col.f32.f16.f16.f32 "
        "{%0,%1,%2,%3}, {%4,%5,%6,%7}, {%8,%9}, {%0,%1,%2,%3};"
        : "+f"(d[0]), "+f"(d[1]), "+f"(d[2]), "+f"(d[3])
        : "r"(a[0]), "r"(a[1]), "r"(a[2]), "r"(a[3]), "r"(b0), "r"(b1));
}

// ---------------------------------------------------------------------------
// Kernel 1: BN stats
// ---------------------------------------------------------------------------
__global__ void bn_stats_kernel(const float* __restrict__ x,
                                const float* __restrict__ gamma,
                                const float* __restrict__ beta) {
    int l = blockIdx.x, t = threadIdx.x;
    float s = 0.f, s2 = 0.f;
    for (int i = t; i < BB * DD; i += 256) {
        int b = i >> 10, d = i & (DD - 1);
        float v = x[(b * LL + l) * DD + d];
        s += v; s2 += v * v;
    }
    __shared__ float rs[256], rs2[256];
    rs[t] = s; rs2[t] = s2;
    __syncthreads();
    for (int o = 128; o > 0; o >>= 1) {
        if (t < o) { rs[t] += rs[t + o]; rs2[t] += rs2[t + o]; }
        __syncthreads();
    }
    if (t == 0) {
        const float inv_n = 1.f / (BB * DD);
        float mean = rs[0] * inv_n;
        float var  = rs2[0] * inv_n - mean * mean;
        float sc = gamma[l] * rsqrtf(var + 1e-5f);
        g_scale[l] = sc;
        g_shift[l] = beta[l] - mean * sc;
    }
}

// ---------------------------------------------------------------------------
// Kernel 2: h = relu(xn@W1+b1) -> fp16 [m][k]
// grid 64 = 16 rowgroups (8 rows) x 4 colgroups (128 cols); 2 rows/thread
// ---------------------------------------------------------------------------
__global__ __launch_bounds__(512) void h_kernel(const float* __restrict__ x,
                                                const float* __restrict__ W1,
                                                const float* __restrict__ b1) {
    __shared__ float xs[8][DD];   // 32 KB
    int t = threadIdx.x;
    int bl0 = (blockIdx.x >> 2) * 8;
    int c0  = (blockIdx.x & 3) * 128;
    for (int i = t; i < 8 * DD; i += 512) {
        int r = i >> 10, d = i & (DD - 1);
        int bl = bl0 + r, l = bl & (LL - 1);
        xs[r][d] = x[bl * DD + d] * g_scale[l] + g_shift[l];
    }
    __syncthreads();
    int col = c0 + (t & 127);
    int r0 = (t >> 7) * 2, r1 = r0 + 1;
    float a0 = 0.f, a1 = 0.f;
#pragma unroll 8
    for (int d = 0; d < DD; ++d) {
        float wv = W1[d * HH + col];
        a0 += xs[r0][d] * wv;
        a1 += xs[r1][d] * wv;
    }
    float bj = b1[col];
    g_h16[(bl0 + r0) * HH + col] = __float2half_rn(fmaxf(a0 + bj, 0.f));
    g_h16[(bl0 + r1) * HH + col] = __float2half_rn(fmaxf(a1 + bj, 0.f));
}

// ---------------------------------------------------------------------------
// HMMA GEMM: both matrices in one grid. v-tiles (bid<NTV) write g_vt fp16;
// y-tiles write out fp32 directly. Single-pass fp16: A16 @ B16 -> f32.
// ---------------------------------------------------------------------------
__global__ __launch_bounds__(256, 2) void gemm_kernel(const float* __restrict__ Wv,
                                                      const float* __restrict__ bv,
                                                      const float* __restrict__ Wy,
                                                      const float* __restrict__ by,
                                                      float* __restrict__ out) {
    extern __shared__ __align__(128) char smem[];
    const int t = threadIdx.x;
    const int lane = t & 31, w = t >> 5;
    const int wm = (w >> 2) * 64, wn = (w & 3) * 32;
    const bool isY = blockIdx.x >= NTV;
    const float* __restrict__ W    = isY ? Wy : Wv;
    const float* __restrict__ bias = isY ? by : bv;
    const int NN  = isY ? SSN : VVN;
    const int n0g = (isY ? blockIdx.x - NTV : blockIdx.x) * 128;
    const unsigned sb = smem_u32(smem);

    const int bk = t >> 3;              // B row (k)
    const int bn = (t & 7) * 16;        // B col base

    float acc[4][4][4];
#pragma unroll
    for (int i = 0; i < 4; ++i)
#pragma unroll
        for (int j = 0; j < 4; ++j)
#pragma unroll
            for (int e = 0; e < 4; ++e) acc[i][j][e] = 0.f;

    uint2 pBc[4];

    auto copyA = [&](int c) {
        unsigned stg = sb + (unsigned)(c & 1) * STAGE_SZ;
        int k0 = c * BKC;
#pragma unroll
        for (int j = 0; j < 2; ++j) {
            int id = t + 256 * j;
            int m = id >> 2, ch = id & 3;
            unsigned off = (unsigned)(m * 64 + ((ch ^ ((m >> 1) & 3))) * 16);
            CP_ASYNC16(stg + A_OFF + off, &g_h16[m * HH + k0 + ch * 8]);
        }
    };
    auto prefB = [&](int c) {
        int k0 = c * BKC;
        const float* wr = W + (size_t)(k0 + bk) * NN + n0g + bn;
#pragma unroll
        for (int j = 0; j < 4; ++j) {
            int gn = n0g + bn + j * 4;
            float4 v = (gn < NN) ? *(const float4*)(wr + j * 4)
                                 : make_float4(0.f, 0.f, 0.f, 0.f);
            __half2 h0 = __floats2half2_rn(v.x, v.y);
            __half2 h1 = __floats2half2_rn(v.z, v.w);
            pBc[j].x = *(unsigned*)&h0;
            pBc[j].y = *(unsigned*)&h1;
        }
    };
    auto stsB = [&](int c) {
        char* st = smem + (c & 1) * STAGE_SZ;
#pragma unroll
        for (int j = 0; j < 4; ++j)
            *(uint2*)(st + B_OFF + bk * 272 + (bn + j * 4) * 2) = pBc[j];
    };

    copyA(0); CP_COMMIT();
    prefB(0); stsB(0);
    CP_WAIT0();
    __syncthreads();

    const unsigned bBase = (unsigned)((lane & 15) * 272 +
                                      (wn + (lane >> 4) * 8) * 2);

    for (int c = 0; c < HH / BKC; ++c) {
        if (c < HH / BKC - 1) {
            prefB(c + 1);
            copyA(c + 1); CP_COMMIT();
        }
        const unsigned stgb = sb + (unsigned)(c & 1) * STAGE_SZ;
#pragma unroll
        for (int ks = 0; ks < 2; ++ks) {
            unsigned ah[4][4], bf[2][4];
#pragma unroll
            for (int mi = 0; mi < 4; ++mi) {
                int row = wm + mi * 16 + (lane & 15);
                int chunk = (ks * 2 + (lane >> 4)) ^ ((row >> 1) & 3);
                ldsm4(ah[mi][0], ah[mi][1], ah[mi][2], ah[mi][3],
                      stgb + A_OFF + row * 64 + chunk * 16);
            }
#pragma unroll
            for (int g = 0; g < 2; ++g)
                ldsm4t(bf[g][0], bf[g][1], bf[g][2], bf[g][3],
                       stgb + B_OFF + bBase + ks * 4352 + g * 32);
#pragma unroll
            for (int mi = 0; mi < 4; ++mi)
#pragma unroll
                for (int nj = 0; nj < 4; ++nj)
                    mma_f16(acc[mi][nj], ah[mi],
                            bf[nj >> 1][(nj & 1) * 2],
                            bf[nj >> 1][(nj & 1) * 2 + 1]);
        }
        if (c < HH / BKC - 1) {
            stsB(c + 1);
            CP_WAIT0();
            __syncthreads();
        }
    }
    __syncthreads();

    if (isY) {
        // direct float2 stores: lane owns (row, 2 consecutive cols)
#pragma unroll
        for (int mi = 0; mi < 4; ++mi)
#pragma unroll
            for (int nj = 0; nj < 4; ++nj) {
                int r0 = wm + mi * 16 + (lane >> 2);
                int col = wn + nj * 8 + (lane & 3) * 2;
                int gn = n0g + col;
                float* d = acc[mi][nj];
                if (gn + 1 < SSN) {
                    float2 bb = *(const float2*)&bias[gn];
                    *(float2*)&out[(size_t)r0 * SSN + gn] =
                        make_float2(d[0] + bb.x, d[1] + bb.y);
                    *(float2*)&out[(size_t)(r0 + 8) * SSN + gn] =
                        make_float2(d[2] + bb.x, d[3] + bb.y);
                } else if (gn < SSN) {
                    float b0 = __ldg(&bias[gn]);
                    out[(size_t)r0 * SSN + gn]       = d[0] + b0;
                    out[(size_t)(r0 + 8) * SSN + gn] = d[2] + b0;
                }
            }
    } else {
        // transpose through smem -> g_vt fp16 [n][m]
        float* ys  = (float*)smem;
        float* b_s = (float*)(smem + BIA_OFF);
#pragma unroll 1
        for (int hf = 0; hf < 2; ++hf) {
            const int h0 = hf * 64;
            if (t < 64) {
                int gn = n0g + h0 + t;
                b_s[t] = (gn < VVN) ? bias[gn] : 0.f;
            }
            if (((w & 3) >> 1) == hf) {
                int wn2 = ((w & 3) & 1) * 32;
#pragma unroll
                for (int mi = 0; mi < 4; ++mi)
#pragma unroll
                    for (int nj = 0; nj < 4; ++nj) {
                        int row = wm + mi * 16 + (lane >> 2);
                        int col = wn2 + nj * 8 + (lane & 3) * 2;
                        float* d = acc[mi][nj];
                        ys[row * YS_PITCH + col]           = d[0];
                        ys[row * YS_PITCH + col + 1]       = d[1];
                        ys[(row + 8) * YS_PITCH + col]     = d[2];
                        ys[(row + 8) * YS_PITCH + col + 1] = d[3];
                    }
            }
            __syncthreads();
            for (int i = t; i < 64 * 64; i += 256) {
                int r2 = i & 63, col = i >> 6;
                int gn = n0g + h0 + col;
                if (gn < VVN) {
                    float bvv = b_s[col];
                    __half2 pv = __floats2half2_rn(
                        ys[(2 * r2) * YS_PITCH + col] + bvv,
                        ys[(2 * r2 + 1) * YS_PITCH + col] + bvv);
                    *(__half2*)&g_vt[(size_t)gn * MM + 2 * r2] = pv;
                }
            }
            __syncthreads();
        }
    }
}

// ---------------------------------------------------------------------------
// Gather kernel: out[m, s] += 0.1 * sum_k w[s,k] * vt[idx[s,k]][m]
// block = 32 s-cols; warp = 4 cols; lane covers 4 m rows (8B of fp16 vt row)
// prefetch distance 2: 8 LDGs in flight during each FMA block
// ---------------------------------------------------------------------------
__global__ __launch_bounds__(256) void gather_kernel(const float* __restrict__ slw,
                                                     const int* __restrict__ slidx,
                                                     float* __restrict__ out) {
    __shared__ float    sacc[32][132];   // pitch 132 f32 = 528 B (16-B aligned)
    __shared__ int      idx_s[1024];
    __shared__ unsigned w2_s[1024];      // packed half2(wk, wk)
    const int t = threadIdx.x, lane = t & 31, w = t >> 5;
    const int s0 = blockIdx.x * 32;

    for (int i = t; i < 1024; i += 256) {
        int gs = s0 + (i >> 5);
        bool ok = (gs < SSN);
        idx_s[i] = ok ? slidx[(size_t)gs * KK + (i & 31)] : 0;
        float wk = ok ? slw[(size_t)gs * KK + (i & 31)] : 0.f;
        __half2 p = __half2half2(__float2half_rn(wk));
        w2_s[i] = *(unsigned*)&p;
    }
    __syncthreads();

    __half2 acc[4][2];
#pragma unroll
    for (int c = 0; c < 4; ++c) {
        acc[c][0] = __half2half2(__ushort_as_half(0));
        acc[c][1] = __half2half2(__ushort_as_half(0));
    }

    const __half* vbase = &g_vt[lane * 4];
    const int ciB = w * 4 * KK;

    uint2 buf0[4], buf1[4];
#pragma unroll
    for (int cj = 0; cj < 4; ++cj) {
        buf0[cj] = *(const uint2*)(vbase + (size_t)idx_s[ciB + cj * KK] * MM);
        buf1[cj] = *(const uint2*)(vbase + (size_t)idx_s[ciB + cj * KK + 1] * MM);
    }

#pragma unroll 8
    for (int k = 0; k < KK; ++k) {
        uint2* cur = (k & 1) ? buf1 : buf0;
        uint2 nxt[4];
        if (k + 2 < KK) {
#pragma unroll
            for (int cj = 0; cj < 4; ++cj)
                nxt[cj] = *(const uint2*)(vbase +
                          (size_t)idx_s[ciB + cj * KK + k + 2] * MM);
        }
#pragma unroll
        for (int cj = 0; cj < 4; ++cj) {
            unsigned wraw = w2_s[ciB + cj * KK + k];
            __half2 wk2 = *(__half2*)&wraw;
            acc[cj][0] = __hfma2(*(__half2*)&cur[cj].x, wk2, acc[cj][0]);
            acc[cj][1] = __hfma2(*(__half2*)&cur[cj].y, wk2, acc[cj][1]);
        }
        if (k + 2 < KK) {
#pragma unroll
            for (int cj = 0; cj < 4; ++cj) cur[cj] = nxt[cj];
        }
    }

    const int mb = lane * 4;
#pragma unroll
    for (int cj = 0; cj < 4; ++cj) {
        float2 f0 = __half22float2(acc[cj][0]);
        float2 f1 = __half22float2(acc[cj][1]);
        *(float4*)&sacc[w * 4 + cj][mb] = make_float4(f0.x, f0.y, f1.x, f1.y);
    }
    __syncthreads();

    for (int i = t; i < 32 * MM; i += 256) {
        int m = i >> 5, col = i & 31;
        int gs = s0 + col;
        if (gs < SSN)
            out[(size_t)m * SSN + gs] += 0.1f * sacc[col][m];
    }
}

// ---------------------------------------------------------------------------
extern "C" void kernel_launch(void* const* d_in, const int* in_sizes, int n_in,
                              void* d_out, int out_size) {
    const float* x     = (const float*)d_in[0];
    const float* gamma = (const float*)d_in[1];
    const float* beta  = (const float*)d_in[2];
    const float* W1    = (const float*)d_in[3];
    const float* b1    = (const float*)d_in[4];
    const float* W2    = (const float*)d_in[5];
    const float* b2    = (const float*)d_in[6];
    const float* Wslm  = (const float*)d_in[7];
    const float* bslm  = (const float*)d_in[8];
    const float* slw   = (const float*)d_in[9];
    const int*   slidx = (const int*)d_in[10];
    float* out = (float*)d_out;

    cudaFuncSetAttribute(gemm_kernel,
                         cudaFuncAttributeMaxDynamicSharedMemorySize, SMEM_BYTES);

    bn_stats_kernel<<<LL, 256>>>(x, gamma, beta);
    h_kernel<<<64, 512>>>(x, W1, b1);
    gemm_kernel<<<NTV + NTY, 256, SMEM_BYTES>>>(Wslm, bslm, W2, b2, out);
    gather_kernel<<<(SSN + 31) / 32, 256>>>(slw, slidx, out);
}

// round 15
// speedup vs baseline: 1.4397x; 1.0870x over previous
#include <cuda_runtime.h>
#include <cuda_bf16.h>
#include <cuda_fp16.h>

#define BB 2
#define LL 64
#define DD 1024
#define HH 512
#define SSN 50000
#define VVN 40000
#define KK 32
#define MM 128
#define BKC 64
#define NTV 313     // ceil(40000/128)
#define NTY 391     // ceil(50000/128)

// ---------------- device scratch ----------------
__device__ float g_scale[LL];
__device__ float g_shift[LL];
__device__ __align__(16) __half g_h16[MM * HH];           // h fp16 [m][k]
__device__ __align__(16) __half g_vt[(size_t)VVN * MM];   // v^T fp16 [V][128]

// ---------------- smem layout (bytes) ----------------
#define A_OFF    0          // [128][64] fp16, 128B rows, SW128 swizzle (16384)
#define B_OFF    16384      // [64][136] fp16, 272B rows (17408)
#define STAGE_SZ 33792      // x2 stages = 67584
#define YS_PITCH 66         // ys[128][66] f32 = 33792 (overlays stage 0)
#define BIA_OFF  67584      // b_s[64]
#define SMEM_BYTES 67840

__device__ __forceinline__ unsigned smem_u32(const void* p) {
    unsigned a;
    asm("{ .reg .u64 t; cvta.to.shared.u64 t, %1; cvt.u32.u64 %0, t; }"
        : "=r"(a) : "l"(p));
    return a;
}
#define CP_ASYNC16(dst, src) \
    asm volatile("cp.async.cg.shared.global [%0], [%1], 16;" :: "r"(dst), "l"(src))
#define CP_COMMIT() asm volatile("cp.async.commit_group;" ::: "memory")
#define CP_WAIT0()  asm volatile("cp.async.wait_group 0;" ::: "memory")

__device__ __forceinline__ void ldsm4(unsigned& r0, unsigned& r1, unsigned& r2,
                                      unsigned& r3, unsigned addr) {
    asm volatile("ldmatrix.sync.aligned.m8n8.x4.shared.b16 {%0,%1,%2,%3}, [%4];"
                 : "=r"(r0), "=r"(r1), "=r"(r2), "=r"(r3) : "r"(addr));
}
__device__ __forceinline__ void ldsm4t(unsigned& r0, unsigned& r1, unsigned& r2,
                                       unsigned& r3, unsigned addr) {
    asm volatile("ldmatrix.sync.aligned.m8n8.x4.trans.shared.b16 {%0,%1,%2,%3}, [%4];"
                 : "=r"(r0), "=r"(r1), "=r"(r2), "=r"(r3) : "r"(addr));
}
__device__ __forceinline__ void mma_f16(float* d, const unsigned* a,
                                        unsigned b0, unsigned b1) {
    asm volatile(
        "mma.sync.aligned.m16n8k16.row.col.f32.f16.f16.f32 "
        "{%0,%1,%2,%3}, {%4,%5,%6,%7}, {%8,%9}, {%0,%1,%2,%3};"
        : "+f"(d[0]), "+f"(d[1]), "+f"(d[2]), "+f"(d[3])
        : "r"(a[0]), "r"(a[1]), "r"(a[2]), "r"(a[3]), "r"(b0), "r"(b1));
}

// ---------------------------------------------------------------------------
// Kernel 1: BN stats
// ---------------------------------------------------------------------------
__global__ void bn_stats_kernel(const float* __restrict__ x,
                                const float* __restrict__ gamma,
                                const float* __restrict__ beta) {
    int l = blockIdx.x, t = threadIdx.x;
    float s = 0.f, s2 = 0.f;
    for (int i = t; i < BB * DD; i += 256) {
        int b = i >> 10, d = i & (DD - 1);
        float v = x[(b * LL + l) * DD + d];
        s += v; s2 += v * v;
    }
    __shared__ float rs[256], rs2[256];
    rs[t] = s; rs2[t] = s2;
    __syncthreads();
    for (int o = 128; o > 0; o >>= 1) {
        if (t < o) { rs[t] += rs[t + o]; rs2[t] += rs2[t + o]; }
        __syncthreads();
    }
    if (t == 0) {
        const float inv_n = 1.f / (BB * DD);
        float mean = rs[0] * inv_n;
        float var  = rs2[0] * inv_n - mean * mean;
        float sc = gamma[l] * rsqrtf(var + 1e-5f);
        g_scale[l] = sc;
        g_shift[l] = beta[l] - mean * sc;
    }
}

// ---------------------------------------------------------------------------
// Kernel 2: h = relu(xn@W1+b1) -> fp16 [m][k]
// grid 64 = 16 rowgroups (8 rows) x 4 colgroups (128 cols); 2 rows/thread
// ---------------------------------------------------------------------------
__global__ __launch_bounds__(512) void h_kernel(const float* __restrict__ x,
                                                const float* __restrict__ W1,
                                                const float* __restrict__ b1) {
    __shared__ float xs[8][DD];   // 32 KB
    int t = threadIdx.x;
    int bl0 = (blockIdx.x >> 2) * 8;
    int c0  = (blockIdx.x & 3) * 128;
    for (int i = t; i < 8 * DD; i += 512) {
        int r = i >> 10, d = i & (DD - 1);
        int bl = bl0 + r, l = bl & (LL - 1);
        xs[r][d] = x[bl * DD + d] * g_scale[l] + g_shift[l];
    }
    __syncthreads();
    int col = c0 + (t & 127);
    int r0 = (t >> 7) * 2, r1 = r0 + 1;
    float a0 = 0.f, a1 = 0.f;
#pragma unroll 8
    for (int d = 0; d < DD; ++d) {
        float wv = W1[d * HH + col];
        a0 += xs[r0][d] * wv;
        a1 += xs[r1][d] * wv;
    }
    float bj = b1[col];
    g_h16[(bl0 + r0) * HH + col] = __float2half_rn(fmaxf(a0 + bj, 0.f));
    g_h16[(bl0 + r1) * HH + col] = __float2half_rn(fmaxf(a1 + bj, 0.f));
}

// ---------------------------------------------------------------------------
// HMMA GEMM: both matrices in one grid. v-tiles (bid<NTV) write g_vt fp16;
// y-tiles write out fp32 directly. Single-pass fp16, BKC=64, double-buffered.
// ---------------------------------------------------------------------------
__global__ __launch_bounds__(256, 2) void gemm_kernel(const float* __restrict__ Wv,
                                                      const float* __restrict__ bv,
                                                      const float* __restrict__ Wy,
                                                      const float* __restrict__ by,
                                                      float* __restrict__ out) {
    extern __shared__ __align__(128) char smem[];
    const int t = threadIdx.x;
    const int lane = t & 31, w = t >> 5;
    const int wm = (w >> 2) * 64, wn = (w & 3) * 32;
    const bool isY = blockIdx.x >= NTV;
    const float* __restrict__ W    = isY ? Wy : Wv;
    const float* __restrict__ bias = isY ? by : bv;
    const int NN  = isY ? SSN : VVN;
    const int n0g = (isY ? blockIdx.x - NTV : blockIdx.x) * 128;
    const unsigned sb = smem_u32(smem);

    const int bk = t >> 3;              // B row (k) base, 0..31
    const int bn = (t & 7) * 16;        // B col base

    float acc[4][4][4];
#pragma unroll
    for (int i = 0; i < 4; ++i)
#pragma unroll
        for (int j = 0; j < 4; ++j)
#pragma unroll
            for (int e = 0; e < 4; ++e) acc[i][j][e] = 0.f;

    uint2 pBc[2][4];   // [k-half][j]

    auto copyA = [&](int c) {
        unsigned stg = sb + (unsigned)(c & 1) * STAGE_SZ;
        int k0 = c * BKC;
#pragma unroll
        for (int j = 0; j < 4; ++j) {
            int id = t + 256 * j;
            int m = id >> 3, ch = id & 7;
            unsigned off = (unsigned)(m * 128 + ((ch ^ (m & 7)) * 16));
            CP_ASYNC16(stg + A_OFF + off, &g_h16[m * HH + k0 + ch * 8]);
        }
    };
    auto prefB = [&](int c) {
        int k0 = c * BKC;
#pragma unroll
        for (int hfk = 0; hfk < 2; ++hfk) {
            const float* wr = W + (size_t)(k0 + bk + hfk * 32) * NN + n0g + bn;
#pragma unroll
            for (int j = 0; j < 4; ++j) {
                int gn = n0g + bn + j * 4;
                float4 v = (gn < NN) ? *(const float4*)(wr + j * 4)
                                     : make_float4(0.f, 0.f, 0.f, 0.f);
                __half2 h0 = __floats2half2_rn(v.x, v.y);
                __half2 h1 = __floats2half2_rn(v.z, v.w);
                pBc[hfk][j].x = *(unsigned*)&h0;
                pBc[hfk][j].y = *(unsigned*)&h1;
            }
        }
    };
    auto stsB = [&](int c) {
        char* st = smem + (c & 1) * STAGE_SZ;
#pragma unroll
        for (int hfk = 0; hfk < 2; ++hfk)
#pragma unroll
            for (int j = 0; j < 4; ++j)
                *(uint2*)(st + B_OFF + (bk + hfk * 32) * 272 + (bn + j * 4) * 2) =
                    pBc[hfk][j];
    };

    copyA(0); CP_COMMIT();
    prefB(0); stsB(0);
    CP_WAIT0();
    __syncthreads();

    const unsigned bBase = (unsigned)((lane & 15) * 272 +
                                      (wn + (lane >> 4) * 8) * 2);

    for (int c = 0; c < HH / BKC; ++c) {
        if (c < HH / BKC - 1) {
            prefB(c + 1);
            copyA(c + 1); CP_COMMIT();
        }
        const unsigned stgb = sb + (unsigned)(c & 1) * STAGE_SZ;
#pragma unroll
        for (int ks = 0; ks < 4; ++ks) {
            unsigned ah[4][4], bf[2][4];
#pragma unroll
            for (int mi = 0; mi < 4; ++mi) {
                int row = wm + mi * 16 + (lane & 15);
                int chunk = (ks * 2 + (lane >> 4)) ^ (row & 7);
                ldsm4(ah[mi][0], ah[mi][1], ah[mi][2], ah[mi][3],
                      stgb + A_OFF + row * 128 + chunk * 16);
            }
#pragma unroll
            for (int g = 0; g < 2; ++g)
                ldsm4t(bf[g][0], bf[g][1], bf[g][2], bf[g][3],
                       stgb + B_OFF + bBase + ks * 4352 + g * 32);
#pragma unroll
            for (int mi = 0; mi < 4; ++mi)
#pragma unroll
                for (int nj = 0; nj < 4; ++nj)
                    mma_f16(acc[mi][nj], ah[mi],
                            bf[nj >> 1][(nj & 1) * 2],
                            bf[nj >> 1][(nj & 1) * 2 + 1]);
        }
        if (c < HH / BKC - 1) {
            stsB(c + 1);
            CP_WAIT0();
            __syncthreads();
        }
    }
    __syncthreads();

    if (isY) {
        // direct float2 stores: lane owns (row, 2 consecutive cols)
#pragma unroll
        for (int mi = 0; mi < 4; ++mi)
#pragma unroll
            for (int nj = 0; nj < 4; ++nj) {
                int r0 = wm + mi * 16 + (lane >> 2);
                int col = wn + nj * 8 + (lane & 3) * 2;
                int gn = n0g + col;
                float* d = acc[mi][nj];
                if (gn + 1 < SSN) {
                    float2 bb = *(const float2*)&bias[gn];
                    *(float2*)&out[(size_t)r0 * SSN + gn] =
                        make_float2(d[0] + bb.x, d[1] + bb.y);
                    *(float2*)&out[(size_t)(r0 + 8) * SSN + gn] =
                        make_float2(d[2] + bb.x, d[3] + bb.y);
                } else if (gn < SSN) {
                    float b0 = __ldg(&bias[gn]);
                    out[(size_t)r0 * SSN + gn]       = d[0] + b0;
                    out[(size_t)(r0 + 8) * SSN + gn] = d[2] + b0;
                }
            }
    } else {
        // transpose through smem -> g_vt fp16 [n][m]
        float* ys  = (float*)smem;
        float* b_s = (float*)(smem + BIA_OFF);
#pragma unroll 1
        for (int hf = 0; hf < 2; ++hf) {
            const int h0 = hf * 64;
            if (t < 64) {
                int gn = n0g + h0 + t;
                b_s[t] = (gn < VVN) ? bias[gn] : 0.f;
            }
            if (((w & 3) >> 1) == hf) {
                int wn2 = ((w & 3) & 1) * 32;
#pragma unroll
                for (int mi = 0; mi < 4; ++mi)
#pragma unroll
                    for (int nj = 0; nj < 4; ++nj) {
                        int row = wm + mi * 16 + (lane >> 2);
                        int col = wn2 + nj * 8 + (lane & 3) * 2;
                        float* d = acc[mi][nj];
                        ys[row * YS_PITCH + col]           = d[0];
                        ys[row * YS_PITCH + col + 1]       = d[1];
                        ys[(row + 8) * YS_PITCH + col]     = d[2];
                        ys[(row + 8) * YS_PITCH + col + 1] = d[3];
                    }
            }
            __syncthreads();
            for (int i = t; i < 64 * 64; i += 256) {
                int r2 = i & 63, col = i >> 6;
                int gn = n0g + h0 + col;
                if (gn < VVN) {
                    float bvv = b_s[col];
                    __half2 pv = __floats2half2_rn(
                        ys[(2 * r2) * YS_PITCH + col] + bvv,
                        ys[(2 * r2 + 1) * YS_PITCH + col] + bvv);
                    *(__half2*)&g_vt[(size_t)gn * MM + 2 * r2] = pv;
                }
            }
            __syncthreads();
        }
    }
}

// ---------------------------------------------------------------------------
// Gather kernel: out[m, s] += 0.1 * sum_k w[s,k] * vt[idx[s,k]][m]
// block = 32 s-cols; warp = 4 cols; lane covers 4 m rows (8B of fp16 vt row)
// prefetch distance 1 (34 regs, occ ~63% — measured best in R13)
// ---------------------------------------------------------------------------
__global__ __launch_bounds__(256) void gather_kernel(const float* __restrict__ slw,
                                                     const int* __restrict__ slidx,
                                                     float* __restrict__ out) {
    __shared__ float    sacc[32][132];   // pitch 132 f32 = 528 B (16-B aligned)
    __shared__ int      idx_s[1024];
    __shared__ unsigned w2_s[1024];      // packed half2(wk, wk)
    const int t = threadIdx.x, lane = t & 31, w = t >> 5;
    const int s0 = blockIdx.x * 32;

    for (int i = t; i < 1024; i += 256) {
        int gs = s0 + (i >> 5);
        bool ok = (gs < SSN);
        idx_s[i] = ok ? slidx[(size_t)gs * KK + (i & 31)] : 0;
        float wk = ok ? slw[(size_t)gs * KK + (i & 31)] : 0.f;
        __half2 p = __half2half2(__float2half_rn(wk));
        w2_s[i] = *(unsigned*)&p;
    }
    __syncthreads();

    __half2 acc[4][2];
#pragma unroll
    for (int c = 0; c < 4; ++c) {
        acc[c][0] = __half2half2(__ushort_as_half(0));
        acc[c][1] = __half2half2(__ushort_as_half(0));
    }

    const __half* vbase = &g_vt[lane * 4];
    const int ciB = w * 4 * KK;

    uint2 cur[4], nxt[4];
#pragma unroll
    for (int cj = 0; cj < 4; ++cj)
        cur[cj] = *(const uint2*)(vbase + (size_t)idx_s[ciB + cj * KK] * MM);

#pragma unroll 4
    for (int k = 0; k < KK; ++k) {
        if (k + 1 < KK) {
#pragma unroll
            for (int cj = 0; cj < 4; ++cj)
                nxt[cj] = *(const uint2*)(vbase +
                          (size_t)idx_s[ciB + cj * KK + k + 1] * MM);
        }
#pragma unroll
        for (int cj = 0; cj < 4; ++cj) {
            unsigned wraw = w2_s[ciB + cj * KK + k];
            __half2 wk2 = *(__half2*)&wraw;
            acc[cj][0] = __hfma2(*(__half2*)&cur[cj].x, wk2, acc[cj][0]);
            acc[cj][1] = __hfma2(*(__half2*)&cur[cj].y, wk2, acc[cj][1]);
        }
#pragma unroll
        for (int cj = 0; cj < 4; ++cj) cur[cj] = nxt[cj];
    }

    const int mb = lane * 4;
#pragma unroll
    for (int cj = 0; cj < 4; ++cj) {
        float2 f0 = __half22float2(acc[cj][0]);
        float2 f1 = __half22float2(acc[cj][1]);
        *(float4*)&sacc[w * 4 + cj][mb] = make_float4(f0.x, f0.y, f1.x, f1.y);
    }
    __syncthreads();

    for (int i = t; i < 32 * MM; i += 256) {
        int m = i >> 5, col = i & 31;
        int gs = s0 + col;
        if (gs < SSN)
            out[(size_t)m * SSN + gs] += 0.1f * sacc[col][m];
    }
}

// ---------------------------------------------------------------------------
extern "C" void kernel_launch(void* const* d_in, const int* in_sizes, int n_in,
                              void* d_out, int out_size) {
    const float* x     = (const float*)d_in[0];
    const float* gamma = (const float*)d_in[1];
    const float* beta  = (const float*)d_in[2];
    const float* W1    = (const float*)d_in[3];
    const float* b1    = (const float*)d_in[4];
    const float* W2    = (const float*)d_in[5];
    const float* b2    = (const float*)d_in[6];
    const float* Wslm  = (const float*)d_in[7];
    const float* bslm  = (const float*)d_in[8];
    const float* slw   = (const float*)d_in[9];
    const int*   slidx = (const int*)d_in[10];
    float* out = (float*)d_out;

    cudaFuncSetAttribute(gemm_kernel,
                         cudaFuncAttributeMaxDynamicSharedMemorySize, SMEM_BYTES);

    bn_stats_kernel<<<LL, 256>>>(x, gamma, beta);
    h_kernel<<<64, 512>>>(x, W1, b1);
    gemm_kernel<<<NTV + NTY, 256, SMEM_BYTES>>>(Wslm, bslm, W2, b2, out);
    gather_kernel<<<(SSN + 31) / 32, 256>>>(slw, slidx, out);
}